// round 6
// baseline (speedup 1.0000x reference)
#include <cuda_runtime.h>
#include <cuda_bf16.h>
#include <cstdint>
#include <cstddef>

#define Bsz 128
#define Tt  256
#define Dd  256
#define Hh  1024
#define Cc  1000

// ---------------- static device scratch (no allocations) ----------------
// xproj layout: [t][j(32)][n(128)][b(128)]  where n = gate*32 + hcol_local,
// global hcol = j*32 + hcol_local. Bias already added.
__device__ float g_xproj[(size_t)Tt * 32 * 128 * 128];   // 512 MB
__device__ float g_h[2][Hh * Bsz];                       // ping-pong h, [k][b]
__device__ float g_c[Hh * Bsz];                          // cell state, [k][b]

// ---------------- packed fp32x2 helpers ----------------
__device__ __forceinline__ unsigned long long pack2(float lo, float hi) {
    unsigned long long r;
    asm("mov.b64 %0, {%1, %2};" : "=l"(r) : "f"(lo), "f"(hi));
    return r;
}
__device__ __forceinline__ void fma2(unsigned long long &acc,
                                     unsigned long long a, unsigned long long b) {
    asm("fma.rn.f32x2 %0, %1, %2, %0;" : "+l"(acc) : "l"(a), "l"(b));
}
__device__ __forceinline__ float sigm(float x) {
    return __fdividef(1.f, 1.f + __expf(-x));
}
__device__ __forceinline__ float tanhx(float x) {
    return 1.f - __fdividef(2.f, __expf(2.f * x) + 1.f);
}

// ---------------- init: zero h0 and c0 (must run every launch) ----------------
__global__ void k_init() {
    int i = blockIdx.x * blockDim.x + threadIdx.x;
    if (i < Hh * Bsz) { g_h[0][i] = 0.f; g_c[i] = 0.f; }
}

// ---------------- phase 1: input projections ----------------
// grid (32 j, 256 t), 256 threads. CTA tile 128n x 128b, thread tile 8n x 8b, K=256.
__global__ __launch_bounds__(256, 2) void k_input_proj(
    const float* __restrict__ x,
    const float* __restrict__ Wg, const float* __restrict__ Wi,
    const float* __restrict__ Wf, const float* __restrict__ Wo,
    const float* __restrict__ bg, const float* __restrict__ bi,
    const float* __restrict__ bf, const float* __restrict__ bo)
{
    __shared__ float Ws[32][128];
    __shared__ float Xs[32][132];
    int j = blockIdx.x, t = blockIdx.y;
    int tid = threadIdx.x;
    int tn = tid & 15, tb = tid >> 4;
    int n0 = tn * 8, b0 = tb * 8;
    int jb = j * 32;
    const float* Wp[4] = {Wg, Wi, Wf, Wo};

    unsigned long long acc[32];
#pragma unroll
    for (int q = 0; q < 32; q++) acc[q] = 0ull;

    for (int kc = 0; kc < Dd / 32; kc++) {
        int k0 = kc * 32;
        // Ws[row][n]: 1024 float4 / 256 threads
#pragma unroll
        for (int p = 0; p < 4; p++) {
            int fi = p * 256 + tid;
            int row = fi >> 5, c4 = fi & 31;
            const float* src = Wp[c4 >> 3] + (size_t)(k0 + row) * Hh + jb + (c4 & 7) * 4;
            *(float4*)&Ws[row][c4 * 4] = *(const float4*)src;
        }
        // Xs[d][b] = x[b][t][k0+d], transposed store
#pragma unroll
        for (int p = 0; p < 4; p++) {
            int fi = p * 256 + tid;
            int b = fi >> 3, d4 = fi & 7;
            float4 v = *(const float4*)&x[((size_t)b * Tt + t) * Dd + k0 + d4 * 4];
            Xs[d4 * 4 + 0][b] = v.x; Xs[d4 * 4 + 1][b] = v.y;
            Xs[d4 * 4 + 2][b] = v.z; Xs[d4 * 4 + 3][b] = v.w;
        }
        __syncthreads();
#pragma unroll 4
        for (int kr = 0; kr < 32; kr++) {
            float4 wA = *(const float4*)&Ws[kr][n0];
            float4 wB = *(const float4*)&Ws[kr][n0 + 4];
            float4 xA = *(const float4*)&Xs[kr][b0];
            float4 xB = *(const float4*)&Xs[kr][b0 + 4];
            unsigned long long w0 = pack2(wA.x, wA.y), w1 = pack2(wA.z, wA.w);
            unsigned long long w2 = pack2(wB.x, wB.y), w3 = pack2(wB.z, wB.w);
            float xv[8] = {xA.x, xA.y, xA.z, xA.w, xB.x, xB.y, xB.z, xB.w};
#pragma unroll
            for (int b = 0; b < 8; b++) {
                unsigned long long xb = pack2(xv[b], xv[b]);
                fma2(acc[0 * 8 + b], w0, xb);
                fma2(acc[1 * 8 + b], w1, xb);
                fma2(acc[2 * 8 + b], w2, xb);
                fma2(acc[3 * 8 + b], w3, xb);
            }
        }
        __syncthreads();
    }
    // epilogue: add bias, store
    float* outp = g_xproj + (((size_t)t * 32 + j) * 128) * 128;
    int gate = n0 >> 5;
    const float* bptr[4] = {bg, bi, bf, bo};
#pragma unroll
    for (int np = 0; np < 4; np++) {
        int n = n0 + 2 * np;
        float bia0 = bptr[gate][jb + (n & 31)];
        float bia1 = bptr[gate][jb + ((n + 1) & 31)];
#pragma unroll
        for (int b = 0; b < 8; b++) {
            float2 v = *(float2*)&acc[np * 8 + b];
            outp[(size_t)n * 128 + b0 + b]       = v.x + bia0;
            outp[(size_t)(n + 1) * 128 + b0 + b] = v.y + bia1;
        }
    }
}

// ---------------- phase 2: one LSTM step ----------------
// grid (4 bblocks, 32 hblocks), 128 threads.
// CTA: 32 hcols x 4 gates (128 n) x 32 batch. Thread tile 8n x 4b.
__global__ __launch_bounds__(128, 1) void k_step(int s,
    const float* __restrict__ Wg, const float* __restrict__ Wi,
    const float* __restrict__ Wf, const float* __restrict__ Wo)
{
    __shared__ float Ws[32][128];
    __shared__ float Hs[32][32];
    __shared__ float Ps[128][33];
    int bb = blockIdx.x, j = blockIdx.y;
    int tid = threadIdx.x;
    int tn = tid & 15, tb = tid >> 4;
    int n0 = tn * 8, b0 = tb * 4;
    int jb = j * 32, bbase = bb * 32;
    const float* Wp[4] = {Wg, Wi, Wf, Wo};
    const float* hin = g_h[s & 1];
    float* hout = g_h[(s + 1) & 1];
    const float* xp = g_xproj + (((size_t)s * 32 + j) * 128) * 128 + bbase;

    // init acc from xproj (bias included)
    unsigned long long acc[16];
#pragma unroll
    for (int np = 0; np < 4; np++) {
        float4 r0 = *(const float4*)&xp[(size_t)(n0 + 2 * np) * 128 + b0];
        float4 r1 = *(const float4*)&xp[(size_t)(n0 + 2 * np + 1) * 128 + b0];
        acc[np * 4 + 0] = pack2(r0.x, r1.x);
        acc[np * 4 + 1] = pack2(r0.y, r1.y);
        acc[np * 4 + 2] = pack2(r0.z, r1.z);
        acc[np * 4 + 3] = pack2(r0.w, r1.w);
    }

    for (int kc = 0; kc < Hh / 32; kc++) {
        int k0 = kc * 32;
        // Ws: 1024 float4 / 128 threads = 8 each
#pragma unroll
        for (int p = 0; p < 8; p++) {
            int fi = p * 128 + tid;
            int row = fi >> 5, c4 = fi & 31;
            const float* src = Wp[c4 >> 3] + (size_t)(k0 + row) * Hh + jb + (c4 & 7) * 4;
            *(float4*)&Ws[row][c4 * 4] = *(const float4*)src;
        }
        // Hs: 256 float4 / 128 threads = 2 each
#pragma unroll
        for (int p = 0; p < 2; p++) {
            int fi = p * 128 + tid;
            int row = fi >> 3, c4 = fi & 7;
            *(float4*)&Hs[row][c4 * 4] =
                *(const float4*)&hin[(size_t)(k0 + row) * Bsz + bbase + c4 * 4];
        }
        __syncthreads();
#pragma unroll 4
        for (int kr = 0; kr < 32; kr++) {
            float4 wA = *(const float4*)&Ws[kr][n0];
            float4 wB = *(const float4*)&Ws[kr][n0 + 4];
            float4 hv = *(const float4*)&Hs[kr][b0];
            unsigned long long w01 = pack2(wA.x, wA.y), w23 = pack2(wA.z, wA.w);
            unsigned long long w45 = pack2(wB.x, wB.y), w67 = pack2(wB.z, wB.w);
            unsigned long long h0 = pack2(hv.x, hv.x), h1 = pack2(hv.y, hv.y);
            unsigned long long h2 = pack2(hv.z, hv.z), h3 = pack2(hv.w, hv.w);
            fma2(acc[0],  w01, h0); fma2(acc[1],  w01, h1);
            fma2(acc[2],  w01, h2); fma2(acc[3],  w01, h3);
            fma2(acc[4],  w23, h0); fma2(acc[5],  w23, h1);
            fma2(acc[6],  w23, h2); fma2(acc[7],  w23, h3);
            fma2(acc[8],  w45, h0); fma2(acc[9],  w45, h1);
            fma2(acc[10], w45, h2); fma2(acc[11], w45, h3);
            fma2(acc[12], w67, h0); fma2(acc[13], w67, h1);
            fma2(acc[14], w67, h2); fma2(acc[15], w67, h3);
        }
        __syncthreads();
    }

    // exchange pre-activations for gate fusion
#pragma unroll
    for (int np = 0; np < 4; np++)
#pragma unroll
        for (int q = 0; q < 4; q++) {
            float2 v = *(float2*)&acc[np * 4 + q];
            Ps[n0 + 2 * np][b0 + q]     = v.x;
            Ps[n0 + 2 * np + 1][b0 + q] = v.y;
        }
    __syncthreads();

    // fusion: each thread handles hcl = tid>>2, 8 consecutive b
    int hcl = tid >> 2, bq = (tid & 3) * 8;
#pragma unroll
    for (int i2 = 0; i2 < 8; i2++) {
        int b = bq + i2;
        float pg = Ps[hcl][b];
        float pi = Ps[32 + hcl][b];
        float pf = Ps[64 + hcl][b];
        float po = Ps[96 + hcl][b];
        size_t ci = (size_t)(jb + hcl) * Bsz + bbase + b;
        float cold = g_c[ci];
        float gg = tanhx(pg), ii = sigm(pi), ff = sigm(pf), oo = sigm(po);
        float cn = gg * ii + cold * ff;
        g_c[ci] = cn;
        hout[ci] = tanhx(cn) * oo;
    }
}

// ---------------- phase 3: final projection + log_softmax ----------------
// one CTA per batch row, 256 threads
__global__ __launch_bounds__(256) void k_final(const float* __restrict__ Wph,
                                               const float* __restrict__ bp,
                                               float* __restrict__ out)
{
    __shared__ float hs[Hh];
    __shared__ float ls[Cc];
    __shared__ float red[256];
    int b = blockIdx.x, tid = threadIdx.x;
    const float* hT = g_h[Tt & 1];   // after 256 steps, final h in buffer 0
    for (int k = tid; k < Hh; k += 256) hs[k] = hT[(size_t)k * Bsz + b];
    __syncthreads();

    float acc[4] = {0.f, 0.f, 0.f, 0.f};
    for (int k = 0; k < Hh; k++) {
        float hk = hs[k];
        const float* wrow = Wph + (size_t)k * Cc;
#pragma unroll
        for (int q = 0; q < 4; q++) {
            int n = tid + q * 256;
            if (n < Cc) acc[q] = fmaf(hk, wrow[n], acc[q]);
        }
    }
    float lmax = -1e30f;
#pragma unroll
    for (int q = 0; q < 4; q++) {
        int n = tid + q * 256;
        if (n < Cc) { float v = acc[q] + bp[n]; ls[n] = v; lmax = fmaxf(lmax, v); }
    }
    red[tid] = lmax; __syncthreads();
    for (int st = 128; st > 0; st >>= 1) {
        if (tid < st) red[tid] = fmaxf(red[tid], red[tid + st]);
        __syncthreads();
    }
    float mx = red[0]; __syncthreads();
    float lsum = 0.f;
#pragma unroll
    for (int q = 0; q < 4; q++) {
        int n = tid + q * 256;
        if (n < Cc) lsum += expf(ls[n] - mx);
    }
    red[tid] = lsum; __syncthreads();
    for (int st = 128; st > 0; st >>= 1) {
        if (tid < st) red[tid] += red[tid + st];
        __syncthreads();
    }
    float lse = logf(red[0]);
#pragma unroll
    for (int q = 0; q < 4; q++) {
        int n = tid + q * 256;
        if (n < Cc) out[(size_t)b * Cc + n] = ls[n] - mx - lse;
    }
}

// ---------------- launch ----------------
extern "C" void kernel_launch(void* const* d_in, const int* in_sizes, int n_in,
                              void* d_out, int out_size) {
    const float* x   = (const float*)d_in[0];
    const float* Wgx = (const float*)d_in[1];
    const float* Wix = (const float*)d_in[2];
    const float* Wfx = (const float*)d_in[3];
    const float* Wox = (const float*)d_in[4];
    const float* Wgh = (const float*)d_in[5];
    const float* Wih = (const float*)d_in[6];
    const float* Wfh = (const float*)d_in[7];
    const float* Woh = (const float*)d_in[8];
    const float* Wph = (const float*)d_in[9];
    const float* bg  = (const float*)d_in[10];
    const float* bi  = (const float*)d_in[11];
    const float* bf  = (const float*)d_in[12];
    const float* bo  = (const float*)d_in[13];
    const float* bp  = (const float*)d_in[14];
    float* out = (float*)d_out;

    k_init<<<(Hh * Bsz + 255) / 256, 256>>>();
    k_input_proj<<<dim3(32, Tt), 256>>>(x, Wgx, Wix, Wfx, Wox, bg, bi, bf, bo);
    for (int s = 0; s < Tt; s++)
        k_step<<<dim3(4, 32), 128>>>(s, Wgh, Wih, Wfh, Woh);
    k_final<<<Bsz, 256>>>(Wph, bp, out);
}

// round 8
// speedup vs baseline: 1.7845x; 1.7845x over previous
#include <cuda_runtime.h>
#include <cuda_bf16.h>
#include <cstdint>
#include <cstddef>

#define Bsz 128
#define Tt  256
#define Dd  256
#define Hh  1024
#define Cc  1000

// ---------------- static device scratch (no allocations) ----------------
// xproj layout: [t][j(32)][n(128)][b(128)], n = gate*32 + hcol_local, bias added.
__device__ float g_xproj[(size_t)Tt * 32 * 128 * 128];   // 512 MB
// h ping-pong, batch-DUPLICATED layout: g_h[p][k*256 + 2*b + {0,1}]
__device__ float g_h[2][(size_t)Hh * 256];
__device__ float g_c[(size_t)Hh * Bsz];                  // cell state [k][b]

// ---------------- packed fp32x2 helpers ----------------
__device__ __forceinline__ unsigned long long pack2(float lo, float hi) {
    unsigned long long r;
    asm("mov.b64 %0, {%1, %2};" : "=l"(r) : "f"(lo), "f"(hi));
    return r;
}
__device__ __forceinline__ void fma2(unsigned long long &acc,
                                     unsigned long long a, unsigned long long b) {
    asm("fma.rn.f32x2 %0, %1, %2, %0;" : "+l"(acc) : "l"(a), "l"(b));
}
__device__ __forceinline__ float sigm(float x) {
    return __fdividef(1.f, 1.f + __expf(-x));
}
__device__ __forceinline__ float tanhx(float x) {
    return 1.f - __fdividef(2.f, __expf(2.f * x) + 1.f);
}
__device__ __forceinline__ void cpa16(uint32_t dst, const void* src) {
    asm volatile("cp.async.cg.shared.global [%0], [%1], 16;" :: "r"(dst), "l"(src));
}
__device__ __forceinline__ void cpa_commit() {
    asm volatile("cp.async.commit_group;");
}
__device__ __forceinline__ void cpa_wait0() {
    asm volatile("cp.async.wait_group 0;");
}

// ---------------- init: zero h0 (dup layout) and c0 ----------------
__global__ void k_init() {
    int i = blockIdx.x * blockDim.x + threadIdx.x;
    if (i < Hh * 256) g_h[0][i] = 0.f;
    if (i < Hh * Bsz) g_c[i] = 0.f;
}

// ---------------- phase 1: input projections ----------------
__global__ __launch_bounds__(256, 2) void k_input_proj(
    const float* __restrict__ x,
    const float* __restrict__ Wg, const float* __restrict__ Wi,
    const float* __restrict__ Wf, const float* __restrict__ Wo,
    const float* __restrict__ bg, const float* __restrict__ bi,
    const float* __restrict__ bf, const float* __restrict__ bo)
{
    __shared__ float Ws[32][128];
    __shared__ float Xs[32][132];
    int j = blockIdx.x, t = blockIdx.y;
    int tid = threadIdx.x;
    int tn = tid & 15, tb = tid >> 4;
    int n0 = tn * 8, b0 = tb * 8;
    int jb = j * 32;

    int c4w = tid & 31;                 // 32 float4 per W row
    int gatew = c4w >> 3;
    const float* Wsel = (gatew < 2) ? (gatew == 0 ? Wg : Wi) : (gatew == 2 ? Wf : Wo);
    const float* wsrc0 = Wsel + jb + (c4w & 7) * 4;

    unsigned long long acc[32];
#pragma unroll
    for (int q = 0; q < 32; q++) acc[q] = 0ull;

    for (int kc = 0; kc < Dd / 32; kc++) {
        int k0 = kc * 32;
#pragma unroll
        for (int p = 0; p < 4; p++) {
            int row = p * 8 + (tid >> 5);
            *(float4*)&Ws[row][c4w * 4] = *(const float4*)(wsrc0 + (size_t)(k0 + row) * Hh);
        }
#pragma unroll
        for (int p = 0; p < 4; p++) {
            int fi = p * 256 + tid;
            int b = fi >> 3, d4 = fi & 7;
            float4 v = *(const float4*)&x[((size_t)b * Tt + t) * Dd + k0 + d4 * 4];
            Xs[d4 * 4 + 0][b] = v.x; Xs[d4 * 4 + 1][b] = v.y;
            Xs[d4 * 4 + 2][b] = v.z; Xs[d4 * 4 + 3][b] = v.w;
        }
        __syncthreads();
#pragma unroll 4
        for (int kr = 0; kr < 32; kr++) {
            float4 wA = *(const float4*)&Ws[kr][n0];
            float4 wB = *(const float4*)&Ws[kr][n0 + 4];
            float4 xA = *(const float4*)&Xs[kr][b0];
            float4 xB = *(const float4*)&Xs[kr][b0 + 4];
            unsigned long long w0 = pack2(wA.x, wA.y), w1 = pack2(wA.z, wA.w);
            unsigned long long w2 = pack2(wB.x, wB.y), w3 = pack2(wB.z, wB.w);
            float xv[8] = {xA.x, xA.y, xA.z, xA.w, xB.x, xB.y, xB.z, xB.w};
#pragma unroll
            for (int b = 0; b < 8; b++) {
                unsigned long long xb = pack2(xv[b], xv[b]);
                fma2(acc[0 * 8 + b], w0, xb);
                fma2(acc[1 * 8 + b], w1, xb);
                fma2(acc[2 * 8 + b], w2, xb);
                fma2(acc[3 * 8 + b], w3, xb);
            }
        }
        __syncthreads();
    }
    float* outp = g_xproj + (((size_t)t * 32 + j) * 128) * 128;
    int gate = n0 >> 5;
    const float* bsel = (gate < 2) ? (gate == 0 ? bg : bi) : (gate == 2 ? bf : bo);
#pragma unroll
    for (int np = 0; np < 4; np++) {
        int n = n0 + 2 * np;
        float bia0 = bsel[jb + (n & 31)];
        float bia1 = bsel[jb + ((n + 1) & 31)];
#pragma unroll
        for (int b = 0; b < 8; b++) {
            float2 v = *(float2*)&acc[np * 8 + b];
            outp[(size_t)n * 128 + b0 + b]       = v.x + bia0;
            outp[(size_t)(n + 1) * 128 + b0 + b] = v.y + bia1;
        }
    }
}

// ---------------- phase 2: one LSTM step, v2 ----------------
// grid (4 bb, 32 j), 256 threads = 2 warpgroups splitting K.
// CTA tile: 128 n (32 hcols x 4 gates) x 32 batch. Thread tile 8n x 4b.
// Dynamic smem: Wsd[2wg][2buf][32][128] | Hsd[2wg][2buf][32][64] | Ps[2][128][33]
#define STEP_SMEM_FLOATS (16384 + 8192 + 2 * 128 * 33)
__global__ __launch_bounds__(256, 1) void k_step(int s,
    const float* __restrict__ Wg, const float* __restrict__ Wi,
    const float* __restrict__ Wf, const float* __restrict__ Wo)
{
    extern __shared__ float sm[];
    float* Wsd = sm;                 // 16384 floats
    float* Hsd = sm + 16384;         // 8192 floats
    float* Ps  = sm + 24576;         // 8448 floats

    int bb = blockIdx.x, j = blockIdx.y;
    int tid = threadIdx.x;
    int wg = tid >> 7;
    int wt = tid & 127;
    int tn = wt & 15, tb = wt >> 4;
    int n0 = tn * 8, b0 = tb * 4;
    int jb = j * 32, bbase = bb * 32;
    const float* hin = g_h[s & 1];
    float* hout = g_h[(s + 1) & 1];

    // per-thread cp.async source bases
    int c4w = wt & 31;              // W: 32 float4/row
    int gatew = c4w >> 3;
    const float* Wsel = (gatew < 2) ? (gatew == 0 ? Wg : Wi) : (gatew == 2 ? Wf : Wo);
    const float* wsrc0 = Wsel + jb + (c4w & 7) * 4;
    int wrow0 = wt >> 5;            // + p*4, p<8
    int c4h = wt & 15;              // H: 16 float4/row (64 dup floats)
    const float* hsrc0 = hin + (size_t)bbase * 2 + c4h * 4;
    int hrow0 = wt >> 4;            // + p*8, p<4

    uint32_t wdstb = (uint32_t)__cvta_generic_to_shared(Wsd + (wg * 2) * 32 * 128);
    uint32_t hdstb = (uint32_t)__cvta_generic_to_shared(Hsd + (wg * 2) * 32 * 64);

    // init acc: wg0 from xproj (bias included), wg1 zero
    unsigned long long acc[16];
    if (wg == 0) {
        const float* xp = g_xproj + (((size_t)s * 32 + j) * 128) * 128 + bbase;
#pragma unroll
        for (int np = 0; np < 4; np++) {
            float4 r0 = *(const float4*)&xp[(size_t)(n0 + 2 * np) * 128 + b0];
            float4 r1 = *(const float4*)&xp[(size_t)(n0 + 2 * np + 1) * 128 + b0];
            acc[np * 4 + 0] = pack2(r0.x, r1.x);
            acc[np * 4 + 1] = pack2(r0.y, r1.y);
            acc[np * 4 + 2] = pack2(r0.z, r1.z);
            acc[np * 4 + 3] = pack2(r0.w, r1.w);
        }
    } else {
#pragma unroll
        for (int q = 0; q < 16; q++) acc[q] = 0ull;
    }

    // prefetch kc=0 into buf 0
    {
        int k0 = wg * 512;
#pragma unroll
        for (int p = 0; p < 8; p++) {
            int row = wrow0 + p * 4;
            cpa16(wdstb + (uint32_t)(row * 128 + c4w * 4) * 4,
                  wsrc0 + (size_t)(k0 + row) * Hh);
        }
#pragma unroll
        for (int p = 0; p < 4; p++) {
            int row = hrow0 + p * 8;
            cpa16(hdstb + (uint32_t)(row * 64 + c4h * 4) * 4,
                  hsrc0 + (size_t)(k0 + row) * 256);
        }
        cpa_commit();
    }

    int buf = 0;
    for (int kcl = 0; kcl < 16; kcl++) {
        cpa_wait0();
        __syncthreads();
        // prefetch next tile into the other buffer; its previous readers
        // retired at the bottom sync of iteration kcl-1.
        if (kcl < 15) {
            int k0 = wg * 512 + (kcl + 1) * 32;
            uint32_t wd = wdstb + (uint32_t)((buf ^ 1) * 32 * 128) * 4;
            uint32_t hd = hdstb + (uint32_t)((buf ^ 1) * 32 * 64) * 4;
#pragma unroll
            for (int p = 0; p < 8; p++) {
                int row = wrow0 + p * 4;
                cpa16(wd + (uint32_t)(row * 128 + c4w * 4) * 4,
                      wsrc0 + (size_t)(k0 + row) * Hh);
            }
#pragma unroll
            for (int p = 0; p < 4; p++) {
                int row = hrow0 + p * 8;
                cpa16(hd + (uint32_t)(row * 64 + c4h * 4) * 4,
                      hsrc0 + (size_t)(k0 + row) * 256);
            }
            cpa_commit();
        }
        const float* Wb = Wsd + (wg * 2 + buf) * 32 * 128;
        const float* Hb = Hsd + (wg * 2 + buf) * 32 * 64;
#pragma unroll 8
        for (int kr = 0; kr < 32; kr++) {
            ulonglong2 wA = *(const ulonglong2*)(Wb + kr * 128 + n0);
            ulonglong2 wB = *(const ulonglong2*)(Wb + kr * 128 + n0 + 4);
            ulonglong2 hA = *(const ulonglong2*)(Hb + kr * 64 + b0 * 2);
            ulonglong2 hB = *(const ulonglong2*)(Hb + kr * 64 + b0 * 2 + 4);
            fma2(acc[0],  wA.x, hA.x); fma2(acc[1],  wA.x, hA.y);
            fma2(acc[2],  wA.x, hB.x); fma2(acc[3],  wA.x, hB.y);
            fma2(acc[4],  wA.y, hA.x); fma2(acc[5],  wA.y, hA.y);
            fma2(acc[6],  wA.y, hB.x); fma2(acc[7],  wA.y, hB.y);
            fma2(acc[8],  wB.x, hA.x); fma2(acc[9],  wB.x, hA.y);
            fma2(acc[10], wB.x, hB.x); fma2(acc[11], wB.x, hB.y);
            fma2(acc[12], wB.y, hA.x); fma2(acc[13], wB.y, hA.y);
            fma2(acc[14], wB.y, hB.x); fma2(acc[15], wB.y, hB.y);
        }
        buf ^= 1;
        if (kcl < 15) __syncthreads();
    }

    // store partials, reduce across warpgroups, fuse gates
    float* myPs = Ps + wg * 128 * 33;
#pragma unroll
    for (int np = 0; np < 4; np++)
#pragma unroll
        for (int q = 0; q < 4; q++) {
            float2 v = *(float2*)&acc[np * 4 + q];
            myPs[(n0 + 2 * np) * 33 + b0 + q]     = v.x;
            myPs[(n0 + 2 * np + 1) * 33 + b0 + q] = v.y;
        }
    __syncthreads();

    int hcl = tid >> 3, bq = (tid & 7) * 4;
#pragma unroll
    for (int i2 = 0; i2 < 4; i2++) {
        int b = bq + i2;
        float pg = Ps[hcl * 33 + b]          + Ps[128 * 33 + hcl * 33 + b];
        float pi = Ps[(32 + hcl) * 33 + b]   + Ps[128 * 33 + (32 + hcl) * 33 + b];
        float pf = Ps[(64 + hcl) * 33 + b]   + Ps[128 * 33 + (64 + hcl) * 33 + b];
        float po = Ps[(96 + hcl) * 33 + b]   + Ps[128 * 33 + (96 + hcl) * 33 + b];
        size_t ci = (size_t)(jb + hcl) * Bsz + bbase + b;
        float cold = g_c[ci];
        float gg = tanhx(pg), ii = sigm(pi), ff = sigm(pf), oo = sigm(po);
        float cn = gg * ii + cold * ff;
        g_c[ci] = cn;
        float hv = tanhx(cn) * oo;
        float2 hh; hh.x = hv; hh.y = hv;
        *(float2*)&hout[(size_t)(jb + hcl) * 256 + (size_t)(bbase + b) * 2] = hh;
    }
}

// ---------------- phase 3: final projection + log_softmax ----------------
__global__ __launch_bounds__(256) void k_final(const float* __restrict__ Wph,
                                               const float* __restrict__ bp,
                                               float* __restrict__ out)
{
    __shared__ float hs[Hh];
    __shared__ float ls[Cc];
    __shared__ float red[256];
    int b = blockIdx.x, tid = threadIdx.x;
    const float* hT = g_h[Tt & 1];          // Tt even -> buffer 0
    for (int k = tid; k < Hh; k += 256) hs[k] = hT[(size_t)k * 256 + (size_t)b * 2];
    __syncthreads();

    float acc[4] = {0.f, 0.f, 0.f, 0.f};
    for (int k = 0; k < Hh; k++) {
        float hk = hs[k];
        const float* wrow = Wph + (size_t)k * Cc;
#pragma unroll
        for (int q = 0; q < 4; q++) {
            int n = tid + q * 256;
            if (n < Cc) acc[q] = fmaf(hk, wrow[n], acc[q]);
        }
    }
    float lmax = -1e30f;
#pragma unroll
    for (int q = 0; q < 4; q++) {
        int n = tid + q * 256;
        if (n < Cc) { float v = acc[q] + bp[n]; ls[n] = v; lmax = fmaxf(lmax, v); }
    }
    red[tid] = lmax; __syncthreads();
    for (int st = 128; st > 0; st >>= 1) {
        if (tid < st) red[tid] = fmaxf(red[tid], red[tid + st]);
        __syncthreads();
    }
    float mx = red[0]; __syncthreads();
    float lsum = 0.f;
#pragma unroll
    for (int q = 0; q < 4; q++) {
        int n = tid + q * 256;
        if (n < Cc) lsum += expf(ls[n] - mx);
    }
    red[tid] = lsum; __syncthreads();
    for (int st = 128; st > 0; st >>= 1) {
        if (tid < st) red[tid] += red[tid + st];
        __syncthreads();
    }
    float lse = logf(red[0]);
#pragma unroll
    for (int q = 0; q < 4; q++) {
        int n = tid + q * 256;
        if (n < Cc) out[(size_t)b * Cc + n] = ls[n] - mx - lse;
    }
}

// ---------------- launch ----------------
extern "C" void kernel_launch(void* const* d_in, const int* in_sizes, int n_in,
                              void* d_out, int out_size) {
    const float* x   = (const float*)d_in[0];
    const float* Wgx = (const float*)d_in[1];
    const float* Wix = (const float*)d_in[2];
    const float* Wfx = (const float*)d_in[3];
    const float* Wox = (const float*)d_in[4];
    const float* Wgh = (const float*)d_in[5];
    const float* Wih = (const float*)d_in[6];
    const float* Wfh = (const float*)d_in[7];
    const float* Woh = (const float*)d_in[8];
    const float* Wph = (const float*)d_in[9];
    const float* bg  = (const float*)d_in[10];
    const float* bi  = (const float*)d_in[11];
    const float* bf  = (const float*)d_in[12];
    const float* bo  = (const float*)d_in[13];
    const float* bp  = (const float*)d_in[14];
    float* out = (float*)d_out;

    // Not a stream operation; idempotent, graph-capture safe.
    cudaFuncSetAttribute(k_step, cudaFuncAttributeMaxDynamicSharedMemorySize,
                         STEP_SMEM_FLOATS * 4);

    k_init<<<(Hh * 256 + 255) / 256, 256>>>();
    k_input_proj<<<dim3(32, Tt), 256>>>(x, Wgx, Wix, Wfx, Wox, bg, bi, bf, bo);
    for (int s = 0; s < Tt; s++)
        k_step<<<dim3(4, 32), 256, STEP_SMEM_FLOATS * 4>>>(s, Wgh, Wih, Wfh, Woh);
    k_final<<<Bsz, 256>>>(Wph, bp, out);
}

// round 9
// speedup vs baseline: 1.8476x; 1.0353x over previous
#include <cuda_runtime.h>
#include <cuda_bf16.h>
#include <cstdint>
#include <cstddef>

#define Bsz 128
#define Tt  256
#define Dd  256
#define Hh  1024
#define Cc  1000

// ---------------- static device scratch (no allocations) ----------------
// xproj layout: [t][j(32)][n(128)][b(128)], n = gate*32 + hcol_local, bias added.
__device__ float g_xproj[(size_t)Tt * 32 * 128 * 128];   // 512 MB
// h ping-pong, batch-DUPLICATED layout: g_h[p][k*256 + 2*b + {0,1}]
__device__ float g_h[2][(size_t)Hh * 256];
__device__ float g_c[(size_t)Hh * Bsz];                  // cell state [k][b]

// ---------------- packed fp32x2 helpers ----------------
__device__ __forceinline__ unsigned long long pack2(float lo, float hi) {
    unsigned long long r;
    asm("mov.b64 %0, {%1, %2};" : "=l"(r) : "f"(lo), "f"(hi));
    return r;
}
__device__ __forceinline__ void fma2(unsigned long long &acc,
                                     unsigned long long a, unsigned long long b) {
    asm("fma.rn.f32x2 %0, %1, %2, %0;" : "+l"(acc) : "l"(a), "l"(b));
}
__device__ __forceinline__ float sigm(float x) {
    return __fdividef(1.f, 1.f + __expf(-x));
}
__device__ __forceinline__ float tanhx(float x) {
    return 1.f - __fdividef(2.f, __expf(2.f * x) + 1.f);
}
__device__ __forceinline__ void cpa16(uint32_t dst, const void* src) {
    asm volatile("cp.async.cg.shared.global [%0], [%1], 16;" :: "r"(dst), "l"(src));
}
__device__ __forceinline__ void cpa_commit() {
    asm volatile("cp.async.commit_group;");
}
__device__ __forceinline__ void cpa_wait0() {
    asm volatile("cp.async.wait_group 0;");
}

// ---------------- init: zero h0 (dup layout) and c0 ----------------
__global__ void k_init() {
    int i = blockIdx.x * blockDim.x + threadIdx.x;
    if (i < Hh * 256) g_h[0][i] = 0.f;
    if (i < Hh * Bsz) g_c[i] = 0.f;
}

// ---------------- phase 1: input projections ----------------
__global__ __launch_bounds__(256, 2) void k_input_proj(
    const float* __restrict__ x,
    const float* __restrict__ Wg, const float* __restrict__ Wi,
    const float* __restrict__ Wf, const float* __restrict__ Wo,
    const float* __restrict__ bg, const float* __restrict__ bi,
    const float* __restrict__ bf, const float* __restrict__ bo)
{
    __shared__ float Ws[32][128];
    __shared__ float Xs[32][132];
    int j = blockIdx.x, t = blockIdx.y;
    int tid = threadIdx.x;
    int tn = tid & 15, tb = tid >> 4;
    int n0 = tn * 8, b0 = tb * 8;
    int jb = j * 32;

    int c4w = tid & 31;                 // 32 float4 per W row
    int gatew = c4w >> 3;
    const float* Wsel = (gatew < 2) ? (gatew == 0 ? Wg : Wi) : (gatew == 2 ? Wf : Wo);
    const float* wsrc0 = Wsel + jb + (c4w & 7) * 4;

    unsigned long long acc[32];
#pragma unroll
    for (int q = 0; q < 32; q++) acc[q] = 0ull;

    for (int kc = 0; kc < Dd / 32; kc++) {
        int k0 = kc * 32;
#pragma unroll
        for (int p = 0; p < 4; p++) {
            int row = p * 8 + (tid >> 5);
            *(float4*)&Ws[row][c4w * 4] = *(const float4*)(wsrc0 + (size_t)(k0 + row) * Hh);
        }
#pragma unroll
        for (int p = 0; p < 4; p++) {
            int fi = p * 256 + tid;
            int b = fi >> 3, d4 = fi & 7;
            float4 v = *(const float4*)&x[((size_t)b * Tt + t) * Dd + k0 + d4 * 4];
            Xs[d4 * 4 + 0][b] = v.x; Xs[d4 * 4 + 1][b] = v.y;
            Xs[d4 * 4 + 2][b] = v.z; Xs[d4 * 4 + 3][b] = v.w;
        }
        __syncthreads();
#pragma unroll 4
        for (int kr = 0; kr < 32; kr++) {
            float4 wA = *(const float4*)&Ws[kr][n0];
            float4 wB = *(const float4*)&Ws[kr][n0 + 4];
            float4 xA = *(const float4*)&Xs[kr][b0];
            float4 xB = *(const float4*)&Xs[kr][b0 + 4];
            unsigned long long w0 = pack2(wA.x, wA.y), w1 = pack2(wA.z, wA.w);
            unsigned long long w2 = pack2(wB.x, wB.y), w3 = pack2(wB.z, wB.w);
            float xv[8] = {xA.x, xA.y, xA.z, xA.w, xB.x, xB.y, xB.z, xB.w};
#pragma unroll
            for (int b = 0; b < 8; b++) {
                unsigned long long xb = pack2(xv[b], xv[b]);
                fma2(acc[0 * 8 + b], w0, xb);
                fma2(acc[1 * 8 + b], w1, xb);
                fma2(acc[2 * 8 + b], w2, xb);
                fma2(acc[3 * 8 + b], w3, xb);
            }
        }
        __syncthreads();
    }
    float* outp = g_xproj + (((size_t)t * 32 + j) * 128) * 128;
    int gate = n0 >> 5;
    const float* bsel = (gate < 2) ? (gate == 0 ? bg : bi) : (gate == 2 ? bf : bo);
#pragma unroll
    for (int np = 0; np < 4; np++) {
        int n = n0 + 2 * np;
        float bia0 = bsel[jb + (n & 31)];
        float bia1 = bsel[jb + ((n + 1) & 31)];
#pragma unroll
        for (int b = 0; b < 8; b++) {
            float2 v = *(float2*)&acc[np * 8 + b];
            outp[(size_t)n * 128 + b0 + b]       = v.x + bia0;
            outp[(size_t)(n + 1) * 128 + b0 + b] = v.y + bia1;
        }
    }
}

// ---------------- phase 2: one LSTM step, v3 (software-pipelined inner loop) ----------------
// grid (4 bb, 32 j), 256 threads = 2 warpgroups splitting K.
// CTA tile: 128 n (32 hcols x 4 gates) x 32 batch. Thread tile 8n x 4b.
// Dynamic smem: Wsd[2wg][2buf][32][128] | Hsd[2wg][2buf][32][64] | Ps[2][128][33]
#define STEP_SMEM_FLOATS (16384 + 8192 + 2 * 128 * 33)
__global__ __launch_bounds__(256, 1) void k_step(int s,
    const float* __restrict__ Wg, const float* __restrict__ Wi,
    const float* __restrict__ Wf, const float* __restrict__ Wo)
{
    extern __shared__ float sm[];
    float* Wsd = sm;                 // 16384 floats
    float* Hsd = sm + 16384;         // 8192 floats
    float* Ps  = sm + 24576;         // 8448 floats

    int bb = blockIdx.x, j = blockIdx.y;
    int tid = threadIdx.x;
    int wg = tid >> 7;
    int wt = tid & 127;
    int tn = wt & 15, tb = wt >> 4;
    int n0 = tn * 8, b0 = tb * 4;
    int jb = j * 32, bbase = bb * 32;
    const float* hin = g_h[s & 1];
    float* hout = g_h[(s + 1) & 1];

    // per-thread cp.async source bases
    int c4w = wt & 31;              // W: 32 float4/row
    int gatew = c4w >> 3;
    const float* Wsel = (gatew < 2) ? (gatew == 0 ? Wg : Wi) : (gatew == 2 ? Wf : Wo);
    const float* wsrc0 = Wsel + jb + (c4w & 7) * 4;
    int wrow0 = wt >> 5;            // + p*4, p<8
    int c4h = wt & 15;              // H: 16 float4/row (64 dup floats)
    const float* hsrc0 = hin + (size_t)bbase * 2 + c4h * 4;
    int hrow0 = wt >> 4;            // + p*8, p<4

    uint32_t wdstb = (uint32_t)__cvta_generic_to_shared(Wsd + (wg * 2) * 32 * 128);
    uint32_t hdstb = (uint32_t)__cvta_generic_to_shared(Hsd + (wg * 2) * 32 * 64);

    // init acc: wg0 from xproj (bias included), wg1 zero
    unsigned long long acc[16];
    if (wg == 0) {
        const float* xp = g_xproj + (((size_t)s * 32 + j) * 128) * 128 + bbase;
#pragma unroll
        for (int np = 0; np < 4; np++) {
            float4 r0 = *(const float4*)&xp[(size_t)(n0 + 2 * np) * 128 + b0];
            float4 r1 = *(const float4*)&xp[(size_t)(n0 + 2 * np + 1) * 128 + b0];
            acc[np * 4 + 0] = pack2(r0.x, r1.x);
            acc[np * 4 + 1] = pack2(r0.y, r1.y);
            acc[np * 4 + 2] = pack2(r0.z, r1.z);
            acc[np * 4 + 3] = pack2(r0.w, r1.w);
        }
    } else {
#pragma unroll
        for (int q = 0; q < 16; q++) acc[q] = 0ull;
    }

    // prefetch kc=0 into buf 0
    {
        int k0 = wg * 512;
#pragma unroll
        for (int p = 0; p < 8; p++) {
            int row = wrow0 + p * 4;
            cpa16(wdstb + (uint32_t)(row * 128 + c4w * 4) * 4,
                  wsrc0 + (size_t)(k0 + row) * Hh);
        }
#pragma unroll
        for (int p = 0; p < 4; p++) {
            int row = hrow0 + p * 8;
            cpa16(hdstb + (uint32_t)(row * 64 + c4h * 4) * 4,
                  hsrc0 + (size_t)(k0 + row) * 256);
        }
        cpa_commit();
    }

    int buf = 0;
    for (int kcl = 0; kcl < 16; kcl++) {
        cpa_wait0();
        __syncthreads();
        // prefetch next tile into the other buffer; its previous readers
        // retired at the bottom sync of iteration kcl-1.
        if (kcl < 15) {
            int k0 = wg * 512 + (kcl + 1) * 32;
            uint32_t wd = wdstb + (uint32_t)((buf ^ 1) * 32 * 128) * 4;
            uint32_t hd = hdstb + (uint32_t)((buf ^ 1) * 32 * 64) * 4;
#pragma unroll
            for (int p = 0; p < 8; p++) {
                int row = wrow0 + p * 4;
                cpa16(wd + (uint32_t)(row * 128 + c4w * 4) * 4,
                      wsrc0 + (size_t)(k0 + row) * Hh);
            }
#pragma unroll
            for (int p = 0; p < 4; p++) {
                int row = hrow0 + p * 8;
                cpa16(hd + (uint32_t)(row * 64 + c4h * 4) * 4,
                      hsrc0 + (size_t)(k0 + row) * 256);
            }
            cpa_commit();
        }
        const float* Wb = Wsd + (wg * 2 + buf) * 32 * 128;
        const float* Hb = Hsd + (wg * 2 + buf) * 32 * 64;

        // ---- software-pipelined FFMA2 core: load kr+1 before FMAing kr ----
        ulonglong2 cwA = *(const ulonglong2*)(Wb + n0);
        ulonglong2 cwB = *(const ulonglong2*)(Wb + n0 + 4);
        ulonglong2 chA = *(const ulonglong2*)(Hb + b0 * 2);
        ulonglong2 chB = *(const ulonglong2*)(Hb + b0 * 2 + 4);
#pragma unroll
        for (int kr = 0; kr < 32; kr++) {
            ulonglong2 nwA, nwB, nhA, nhB;
            if (kr < 31) {
                nwA = *(const ulonglong2*)(Wb + (kr + 1) * 128 + n0);
                nwB = *(const ulonglong2*)(Wb + (kr + 1) * 128 + n0 + 4);
                nhA = *(const ulonglong2*)(Hb + (kr + 1) * 64 + b0 * 2);
                nhB = *(const ulonglong2*)(Hb + (kr + 1) * 64 + b0 * 2 + 4);
            }
            fma2(acc[0],  cwA.x, chA.x); fma2(acc[1],  cwA.x, chA.y);
            fma2(acc[2],  cwA.x, chB.x); fma2(acc[3],  cwA.x, chB.y);
            fma2(acc[4],  cwA.y, chA.x); fma2(acc[5],  cwA.y, chA.y);
            fma2(acc[6],  cwA.y, chB.x); fma2(acc[7],  cwA.y, chB.y);
            fma2(acc[8],  cwB.x, chA.x); fma2(acc[9],  cwB.x, chA.y);
            fma2(acc[10], cwB.x, chB.x); fma2(acc[11], cwB.x, chB.y);
            fma2(acc[12], cwB.y, chA.x); fma2(acc[13], cwB.y, chA.y);
            fma2(acc[14], cwB.y, chB.x); fma2(acc[15], cwB.y, chB.y);
            if (kr < 31) { cwA = nwA; cwB = nwB; chA = nhA; chB = nhB; }
        }
        buf ^= 1;
        if (kcl < 15) __syncthreads();
    }

    // store partials, reduce across warpgroups, fuse gates
    float* myPs = Ps + wg * 128 * 33;
#pragma unroll
    for (int np = 0; np < 4; np++)
#pragma unroll
        for (int q = 0; q < 4; q++) {
            float2 v = *(float2*)&acc[np * 4 + q];
            myPs[(n0 + 2 * np) * 33 + b0 + q]     = v.x;
            myPs[(n0 + 2 * np + 1) * 33 + b0 + q] = v.y;
        }
    __syncthreads();

    int hcl = tid >> 3, bq = (tid & 7) * 4;
#pragma unroll
    for (int i2 = 0; i2 < 4; i2++) {
        int b = bq + i2;
        float pg = Ps[hcl * 33 + b]          + Ps[128 * 33 + hcl * 33 + b];
        float pi = Ps[(32 + hcl) * 33 + b]   + Ps[128 * 33 + (32 + hcl) * 33 + b];
        float pf = Ps[(64 + hcl) * 33 + b]   + Ps[128 * 33 + (64 + hcl) * 33 + b];
        float po = Ps[(96 + hcl) * 33 + b]   + Ps[128 * 33 + (96 + hcl) * 33 + b];
        size_t ci = (size_t)(jb + hcl) * Bsz + bbase + b;
        float cold = g_c[ci];
        float gg = tanhx(pg), ii = sigm(pi), ff = sigm(pf), oo = sigm(po);
        float cn = gg * ii + cold * ff;
        g_c[ci] = cn;
        float hv = tanhx(cn) * oo;
        float2 hh; hh.x = hv; hh.y = hv;
        *(float2*)&hout[(size_t)(jb + hcl) * 256 + (size_t)(bbase + b) * 2] = hh;
    }
}

// ---------------- phase 3: final projection + log_softmax ----------------
__global__ __launch_bounds__(256) void k_final(const float* __restrict__ Wph,
                                               const float* __restrict__ bp,
                                               float* __restrict__ out)
{
    __shared__ float hs[Hh];
    __shared__ float ls[Cc];
    __shared__ float red[256];
    int b = blockIdx.x, tid = threadIdx.x;
    const float* hT = g_h[Tt & 1];          // Tt even -> buffer 0
    for (int k = tid; k < Hh; k += 256) hs[k] = hT[(size_t)k * 256 + (size_t)b * 2];
    __syncthreads();

    float acc[4] = {0.f, 0.f, 0.f, 0.f};
    for (int k = 0; k < Hh; k++) {
        float hk = hs[k];
        const float* wrow = Wph + (size_t)k * Cc;
#pragma unroll
        for (int q = 0; q < 4; q++) {
            int n = tid + q * 256;
            if (n < Cc) acc[q] = fmaf(hk, wrow[n], acc[q]);
        }
    }
    float lmax = -1e30f;
#pragma unroll
    for (int q = 0; q < 4; q++) {
        int n = tid + q * 256;
        if (n < Cc) { float v = acc[q] + bp[n]; ls[n] = v; lmax = fmaxf(lmax, v); }
    }
    red[tid] = lmax; __syncthreads();
    for (int st = 128; st > 0; st >>= 1) {
        if (tid < st) red[tid] = fmaxf(red[tid], red[tid + st]);
        __syncthreads();
    }
    float mx = red[0]; __syncthreads();
    float lsum = 0.f;
#pragma unroll
    for (int q = 0; q < 4; q++) {
        int n = tid + q * 256;
        if (n < Cc) lsum += expf(ls[n] - mx);
    }
    red[tid] = lsum; __syncthreads();
    for (int st = 128; st > 0; st >>= 1) {
        if (tid < st) red[tid] += red[tid + st];
        __syncthreads();
    }
    float lse = logf(red[0]);
#pragma unroll
    for (int q = 0; q < 4; q++) {
        int n = tid + q * 256;
        if (n < Cc) out[(size_t)b * Cc + n] = ls[n] - mx - lse;
    }
}

// ---------------- launch ----------------
extern "C" void kernel_launch(void* const* d_in, const int* in_sizes, int n_in,
                              void* d_out, int out_size) {
    const float* x   = (const float*)d_in[0];
    const float* Wgx = (const float*)d_in[1];
    const float* Wix = (const float*)d_in[2];
    const float* Wfx = (const float*)d_in[3];
    const float* Wox = (const float*)d_in[4];
    const float* Wgh = (const float*)d_in[5];
    const float* Wih = (const float*)d_in[6];
    const float* Wfh = (const float*)d_in[7];
    const float* Woh = (const float*)d_in[8];
    const float* Wph = (const float*)d_in[9];
    const float* bg  = (const float*)d_in[10];
    const float* bi  = (const float*)d_in[11];
    const float* bf  = (const float*)d_in[12];
    const float* bo  = (const float*)d_in[13];
    const float* bp  = (const float*)d_in[14];
    float* out = (float*)d_out;

    // Not a stream operation; idempotent, graph-capture safe.
    cudaFuncSetAttribute(k_step, cudaFuncAttributeMaxDynamicSharedMemorySize,
                         STEP_SMEM_FLOATS * 4);

    k_init<<<(Hh * 256 + 255) / 256, 256>>>();
    k_input_proj<<<dim3(32, Tt), 256>>>(x, Wgx, Wix, Wfx, Wox, bg, bi, bf, bo);
    for (int s = 0; s < Tt; s++)
        k_step<<<dim3(4, 32), 256, STEP_SMEM_FLOATS * 4>>>(s, Wgh, Wih, Wfh, Woh);
    k_final<<<Bsz, 256>>>(Wph, bp, out);
}